// round 14
// baseline (speedup 1.0000x reference)
#include <cuda_runtime.h>
#include <cuda_fp16.h>
#include <math.h>
#include <stdint.h>

// ---------------- problem constants ----------------
#define DIMC   2048
#define NHEADS 2
#define HDIM   1024
#define BATCH  4
#define SEQ    2048
#define M1     (BATCH*SEQ)   // 8192
#define QKVN   (3*DIMC)      // 6144

__device__ __forceinline__ uint32_t smem_u32(const void* p) {
    uint32_t a;
    asm("{ .reg .u64 t; cvta.to.shared.u64 t, %1; cvt.u32.u64 %0, t; }" : "=r"(a) : "l"(p));
    return a;
}

#define CP_ASYNC16(dst, src) \
    asm volatile("cp.async.cg.shared.global [%0], [%1], 16;" :: "r"(dst), "l"(src) : "memory")
#define CP_COMMIT() asm volatile("cp.async.commit_group;" ::: "memory")
#define CP_WAIT2()  asm volatile("cp.async.wait_group 2;" ::: "memory")

#define LDMATRIX_X4(r0, r1, r2, r3, addr) \
    asm volatile("ldmatrix.sync.aligned.m8n8.x4.shared.b16 {%0,%1,%2,%3}, [%4];" \
        : "=r"(r0), "=r"(r1), "=r"(r2), "=r"(r3) : "r"(addr))

#define MMA_F16(c, a, b0, b1) \
    asm volatile("mma.sync.aligned.m16n8k16.row.col.f32.f16.f16.f32 " \
        "{%0,%1,%2,%3}, {%4,%5,%6,%7}, {%8,%9}, {%0,%1,%2,%3};" \
        : "+f"((c)[0]), "+f"((c)[1]), "+f"((c)[2]), "+f"((c)[3]) \
        : "r"((a)[0]), "r"((a)[1]), "r"((a)[2]), "r"((a)[3]), "r"(b0), "r"(b1))

// ---------------- scratch ----------------
__device__ __align__(128) __half g_qkvh[(size_t)M1 * QKVN];
__device__ float g_s  [(size_t)8 * SEQ * SEQ];
__device__ float g_ctab[SEQ * 512];
__device__ float g_stab[SEQ * 512];
__device__ __align__(128) __half g_xf [(size_t)M1*DIMC];
__device__ __align__(128) __half g_wqh[(size_t)QKVN*DIMC];
__device__ __align__(128) __half g_owh[(size_t)DIMC*DIMC];
__device__ __align__(128) __half g_qf [(size_t)8*SEQ*HDIM];
__device__ __align__(128) __half g_kh [(size_t)8*SEQ*HDIM];
__device__ __align__(128) __half g_vth[(size_t)8*HDIM*SEQ];
__device__ __align__(128) __half g_pf [(size_t)8*SEQ*SEQ];
__device__ __align__(128) __half g_vhf[(size_t)M1*DIMC];

// ---------------- RoPE tables (fp32) ----------------
__global__ void rope_tab_kernel() {
    int idx = blockIdx.x * blockDim.x + threadIdx.x;
    int d = idx & 511, l = idx >> 9;
    float inv = expf((float)(2 * d) * (-9.210340371976184f / 1024.0f));
    float th  = (float)l * inv;
    g_ctab[idx] = cosf(th);
    g_stab[idx] = sinf(th);
}

// ---------------- fused fp32 -> fp16 for 3 arrays ----------------
__global__ void conv3_h(const float* __restrict__ a0, __half* __restrict__ o0, int n0,
                        const float* __restrict__ a1, __half* __restrict__ o1, int n1,
                        const float* __restrict__ a2, __half* __restrict__ o2, int n2) {
    int i = blockIdx.x * 256 + threadIdx.x;
    const float* src; __half* dst;
    if (i < n0)           { src = a0; dst = o0; }
    else if (i < n0 + n1) { src = a1; dst = o1; i -= n0; }
    else                  { src = a2; dst = o2; i -= n0 + n1; }
    float4 v = ((const float4*)src)[i];
    union { __half b[4]; uint2 u; } H;
    H.b[0] = __float2half_rn(v.x); H.b[1] = __float2half_rn(v.y);
    H.b[2] = __float2half_rn(v.z); H.b[3] = __float2half_rn(v.w);
    ((uint2*)dst)[i] = H.u;
}

// ---------------- fused RoPE + V transpose ----------------
__global__ void rope_vt_fused(const __half* __restrict__ qkvh,
                              __half* __restrict__ qf, __half* __restrict__ kh,
                              float* __restrict__ kout, float* __restrict__ vout,
                              __half* __restrict__ vth) {
    __shared__ __half vt1[32][34], vt2[32][34];
    int z = blockIdx.z;
    int b = z >> 1, h = z & 1;
    int l0 = blockIdx.x * 32, d0 = blockIdx.y * 32;
    int tx = threadIdx.x, ty = threadIdx.y;

    #pragma unroll
    for (int j = 0; j < 32; j += 8) {
        int l = l0 + ty + j;
        int d = d0 + tx;
        const __half* row = qkvh + (size_t)(b * SEQ + l) * QKVN + h * HDIM;
        float q1 = __half2float(row[d]),            q2 = __half2float(row[d + 512]);
        float k1 = __half2float(row[DIMC + d]),     k2 = __half2float(row[DIMC + d + 512]);
        __half v1 = row[2*DIMC + d],                v2 = row[2*DIMC + d + 512];

        int ti = (l << 9) + d;
        float c = g_ctab[ti], s = g_stab[ti];
        float rq1 = q1*c - q2*s, rq2 = q1*s + q2*c;
        float rk1 = k1*c - k2*s, rk2 = k1*s + k2*c;

        size_t o = (size_t)(z * SEQ + l) * HDIM + d;
        qf[o]        = __float2half_rn(rq1);
        qf[o + 512]  = __float2half_rn(rq2);
        kh[o]        = __float2half_rn(rk1);
        kh[o + 512]  = __float2half_rn(rk2);
        kout[o]       = rk1;
        kout[o + 512] = rk2;
        vout[o]       = __half2float(v1);
        vout[o + 512] = __half2float(v2);

        vt1[tx][ty + j] = v1;
        vt2[tx][ty + j] = v2;
    }
    __syncthreads();
    #pragma unroll
    for (int j = 0; j < 32; j += 8) {
        int dl = ty + j;
        int l  = l0 + tx;
        vth[((size_t)z * HDIM + d0 + dl)       * SEQ + l] = vt1[dl][tx];
        vth[((size_t)z * HDIM + d0 + 512 + dl) * SEQ + l] = vt2[dl][tx];
    }
}

// ---------------- causal softmax -> fp16 P ----------------
__global__ void softmax_h(const float* __restrict__ S, __half* __restrict__ P) {
    int row = blockIdx.x;
    int l = row & (SEQ - 1);
    const float* p = S + (size_t)row * SEQ;
    int t = threadIdx.x;
    int nproc = (l | 127) + 1;
    bool act = (t * 8) < nproc;

    float v[8];
    float m = -1e30f;
    if (act) {
        float4 v0 = *(const float4*)(p + t * 8);
        float4 v1 = *(const float4*)(p + t * 8 + 4);
        v[0]=v0.x; v[1]=v0.y; v[2]=v0.z; v[3]=v0.w;
        v[4]=v1.x; v[5]=v1.y; v[6]=v1.z; v[7]=v1.w;
        #pragma unroll
        for (int j = 0; j < 8; j++)
            if (t * 8 + j <= l) m = fmaxf(m, v[j]);
    }
    __shared__ float red[256];
    red[t] = m; __syncthreads();
    #pragma unroll
    for (int s = 128; s > 0; s >>= 1) { if (t < s) red[t] = fmaxf(red[t], red[t + s]); __syncthreads(); }
    float mx = red[0]; __syncthreads();

    float sum = 0.f;
    if (act) {
        #pragma unroll
        for (int j = 0; j < 8; j++) {
            v[j] = (t * 8 + j <= l) ? __expf(v[j] - mx) : 0.f;
            sum += v[j];
        }
    }
    red[t] = sum; __syncthreads();
    #pragma unroll
    for (int s = 128; s > 0; s >>= 1) { if (t < s) red[t] += red[t + s]; __syncthreads(); }
    float inv = 1.0f / red[0];

    if (act) {
        union { __half b[8]; uint4 u; } H;
        #pragma unroll
        for (int j = 0; j < 8; j++) H.b[j] = __float2half_rn(v[j] * inv);
        *(uint4*)(P + (size_t)row * SEQ + t * 8) = H.u;
    }
}

// ---------------- warp-MMA fp16 GEMM, 128x64 tiles (occ 2, 4-stage, 1 sync/chunk) ----------------
// C = alpha*(A@B^T) (+bias). A=[M,K] K-major fp16, B=[N,K] K-major fp16.
// Block 128x64x32, 8 warps (4x2), warp tile 32x32, 4-stage cp.async ring, 2 CTAs/SM.
// CAUSAL: 0 none; 1 scores: triangular grid of 64-wide tiles, elementwise diag mask;
//         2 K-limit row0+128 with longest-first row order.
// EPI: 0 -> fp32 C0; 1 -> fp16 C0.
#define KPAD   40
#define MATB_A (128 * KPAD * 2)    // 10240 B
#define MATB_B (64 * KPAD * 2)     // 5120 B
#define STGB   (MATB_A + MATB_B)   // 15360 B per stage
#define NSTG   4
#define SMEM_MMA (NSTG * STGB)     // 61440 B -> 2 CTAs/SM

__device__ __forceinline__ void load_stage_async(uint32_t sbase,
    const __half* A, const __half* B,
    int lda, int ldb, int row0, int col0, int k0)
{
    const int t = threadIdx.x;
    #pragma unroll
    for (int i = 0; i < 3; i++) {
        int s = t + i * 256;        // 0..767
        if (s < 512) {
            int row = s >> 2, c16 = s & 3;
            const __half* src = A + (size_t)(row0 + row) * lda + k0 + c16 * 8;
            CP_ASYNC16(sbase + row * (KPAD * 2) + c16 * 16, src);
        } else {
            int idx = s - 512;
            int row = idx >> 2, c16 = idx & 3;
            const __half* src = B + (size_t)(col0 + row) * ldb + k0 + c16 * 8;
            CP_ASYNC16(sbase + MATB_A + row * (KPAD * 2) + c16 * 16, src);
        }
    }
}

template<int CAUSAL, int EPI>
__global__ void __launch_bounds__(256, 2) gemm_mma(
    const __half* __restrict__ A, const __half* __restrict__ B,
    const float* __restrict__ bias,
    void* __restrict__ C0,
    int K, int lda, int ldb, int ldc,
    long sA, long sB, long sCo, long sCi, int zdiv, float alpha)
{
    extern __shared__ char smem[];
    const int tid = threadIdx.x;
    const int wid = tid >> 5;
    const int lid = tid & 31;
    const int bz = blockIdx.z;

    int row0, col0;
    if (CAUSAL == 1) {
        // triangular decode over 64-wide col tiles: tiles per row r = 2(r+1),
        // cumulative = r(r+1); blockIdx.x = r(r+1) + c
        int t = blockIdx.x;
        int r = (int)((sqrtf(4.f * t + 1.f) - 1.f) * 0.5f);
        while ((r + 1) * (r + 2) <= t) r++;
        while (r * (r + 1) > t) r--;
        row0 = r * 128;
        col0 = (t - r * (r + 1)) * 64;
    } else if (CAUSAL == 2) {
        row0 = (gridDim.y - 1 - blockIdx.y) * 128;   // longest-first
        col0 = blockIdx.x * 64;
    } else {
        row0 = blockIdx.y * 128;
        col0 = blockIdx.x * 64;
    }

    const size_t zoffC = (size_t)(bz / zdiv) * sCo + (size_t)(bz % zdiv) * sCi;
    A += (size_t)bz * sA;
    B += (size_t)bz * sB;

    int Keff = (CAUSAL == 2) ? min(K, row0 + 128) : K;
    const int nc = Keff >> 5;

    const uint32_t sb = smem_u32(smem);
    const int wm = (wid & 3) * 32;
    const int wn = (wid >> 2) * 32;
    const int lrow = lid & 15;
    const int lcol = (lid >> 4) << 3;

    float acc[2][4][4];
    #pragma unroll
    for (int mt = 0; mt < 2; mt++)
        #pragma unroll
        for (int nt = 0; nt < 4; nt++)
            #pragma unroll
            for (int r = 0; r < 4; r++) acc[mt][nt][r] = 0.f;

    #pragma unroll
    for (int s = 0; s < 3; s++) {
        if (s < nc) load_stage_async(sb + s * STGB, A, B, lda, ldb, row0, col0, s << 5);
        CP_COMMIT();
    }

    for (int c = 0; c < nc; c++) {
        CP_WAIT2();
        __syncthreads();
        if (c + 3 < nc)
            load_stage_async(sb + ((c + 3) & 3) * STGB, A, B,
                             lda, ldb, row0, col0, (c + 3) << 5);
        CP_COMMIT();

        uint32_t stg = sb + (c & 3) * STGB;
        #pragma unroll
        for (int kk = 0; kk < 32; kk += 16) {
            uint32_t af[2][4], bf[2][4];
            #pragma unroll
            for (int mt = 0; mt < 2; mt++) {
                uint32_t ra = stg + ((wm + mt * 16 + lrow) * KPAD + kk + lcol) * 2;
                LDMATRIX_X4(af[mt][0], af[mt][1], af[mt][2], af[mt][3], ra);
            }
            #pragma unroll
            for (int g = 0; g < 2; g++) {
                uint32_t rb = stg + MATB_A + ((wn + g * 16 + lrow) * KPAD + kk + lcol) * 2;
                LDMATRIX_X4(bf[g][0], bf[g][1], bf[g][2], bf[g][3], rb);
            }
            #pragma unroll
            for (int mt = 0; mt < 2; mt++)
                #pragma unroll
                for (int nt = 0; nt < 4; nt++) {
                    int g = nt >> 1, o = nt & 1;
                    MMA_F16(acc[mt][nt], af[mt], bf[g][o], bf[g][o + 2]);
                }
        }
    }

    // ---------------- epilogue ----------------
    const bool diag = (CAUSAL == 1) && (col0 + 63 > row0);
    #pragma unroll
    for (int mt = 0; mt < 2; mt++) {
        #pragma unroll
        for (int nt = 0; nt < 4; nt++) {
            int gr0 = row0 + wm + mt * 16 + (lid >> 2);
            int gc  = col0 + wn + nt * 8 + (lid & 3) * 2;
            #pragma unroll
            for (int half = 0; half < 2; half++) {
                int gr = gr0 + half * 8;
                float v0 = acc[mt][nt][2 * half]     * alpha;
                float v1 = acc[mt][nt][2 * half + 1] * alpha;
                if (bias) { v0 += bias[gc]; v1 += bias[gc + 1]; }
                if (diag) {
                    if (gc     > gr) v0 = -1e9f;
                    if (gc + 1 > gr) v1 = -1e9f;
                }
                if (EPI == 0) {
                    float* C = (float*)C0 + zoffC + (size_t)gr * ldc + gc;
                    *(float2*)C = make_float2(v0, v1);
                } else {
                    __half* C = (__half*)C0 + zoffC + (size_t)gr * ldc + gc;
                    union { __half b[2]; uint32_t u; } H;
                    H.b[0] = __float2half_rn(v0);
                    H.b[1] = __float2half_rn(v1);
                    *(uint32_t*)C = H.u;
                }
            }
        }
    }
}

// ---------------- launch ----------------
extern "C" void kernel_launch(void* const* d_in, const int* in_sizes, int n_in,
                              void* d_out, int out_size) {
    const float* x      = (const float*)d_in[0];
    const float* Wqkv_w = (const float*)d_in[2];
    const float* Wqkv_b = (const float*)d_in[3];
    const float* out_w  = (const float*)d_in[4];
    const float* out_b  = (const float*)d_in[5];

    float* out  = (float*)d_out;
    float* kout = out  + (size_t)M1 * DIMC;
    float* vout = kout + (size_t)8 * SEQ * HDIM;

    float *S;
    __half *qkvh,*xf,*wqh,*owh,*qf,*kh,*vth,*pf,*vhf;
    cudaGetSymbolAddress((void**)&qkvh, g_qkvh);
    cudaGetSymbolAddress((void**)&S,    g_s);
    cudaGetSymbolAddress((void**)&xf,   g_xf);
    cudaGetSymbolAddress((void**)&wqh,  g_wqh);
    cudaGetSymbolAddress((void**)&owh,  g_owh);
    cudaGetSymbolAddress((void**)&qf,   g_qf);
    cudaGetSymbolAddress((void**)&kh,   g_kh);
    cudaGetSymbolAddress((void**)&vth,  g_vth);
    cudaGetSymbolAddress((void**)&pf,   g_pf);
    cudaGetSymbolAddress((void**)&vhf,  g_vhf);

    cudaFuncSetAttribute(gemm_mma<0,0>, cudaFuncAttributeMaxDynamicSharedMemorySize, SMEM_MMA);
    cudaFuncSetAttribute(gemm_mma<0,1>, cudaFuncAttributeMaxDynamicSharedMemorySize, SMEM_MMA);
    cudaFuncSetAttribute(gemm_mma<1,0>, cudaFuncAttributeMaxDynamicSharedMemorySize, SMEM_MMA);
    cudaFuncSetAttribute(gemm_mma<2,1>, cudaFuncAttributeMaxDynamicSharedMemorySize, SMEM_MMA);

    // 1) RoPE tables (fp32)
    rope_tab_kernel<<<SEQ, 512>>>();

    // 2) fused conversion of x, Wqkv_w, out_w to fp16 (one launch)
    {
        int n0 = (int)((size_t)M1 * DIMC / 4);
        int n1 = (int)((size_t)QKVN * DIMC / 4);
        int n2 = (int)((size_t)DIMC * DIMC / 4);
        conv3_h<<<(n0 + n1 + n2) / 256, 256>>>(x, xf, n0, Wqkv_w, wqh, n1, out_w, owh, n2);
    }

    // 3) QKV = x @ Wqkv^T + b  -> fp16 qkv  [8192 x 6144 x 2048]
    gemm_mma<0,1><<<dim3(QKVN/64, M1/128, 1), 256, SMEM_MMA>>>(
        xf, wqh, Wqkv_b, qkvh,
        DIMC, DIMC, DIMC, QKVN, 0, 0, 0, 0, 1, 1.0f);

    // 4) fused RoPE + V transpose: qf/kh fp16, kout/vout fp32, vth fp16
    rope_vt_fused<<<dim3(SEQ/32, 512/32, 8), dim3(32, 8)>>>(
        qkvh, qf, kh, kout, vout, vth);

    // 5) S = (1/32) q @ k^T  per head; triangular grid of 64-wide tiles (272/head)
    gemm_mma<1,0><<<dim3(272, 1, 8), 256, SMEM_MMA>>>(
        qf, kh, nullptr, S,
        HDIM, HDIM, HDIM, SEQ,
        (long)SEQ*HDIM, (long)SEQ*HDIM, (long)SEQ*SEQ, 0, 1, 0.03125f);

    // 6) causal softmax -> fp16 P (zero-fill to PV K-limit)
    softmax_h<<<8 * SEQ, 256>>>(S, pf);

    // 7) VH = P @ V (via Vt), causal K-limit, longest-first; fp16 out to (B,L,D)
    gemm_mma<2,1><<<dim3(HDIM/64, SEQ/128, 8), 256, SMEM_MMA>>>(
        pf, vth, nullptr, vhf,
        SEQ, SEQ, SEQ, DIMC,
        (long)SEQ*SEQ, (long)HDIM*SEQ, (long)SEQ*DIMC, (long)HDIM, NHEADS, 1.0f);

    // 8) out = VH @ out_w^T + out_b  [8192 x 2048 x 2048]
    gemm_mma<0,0><<<dim3(DIMC/64, M1/128, 1), 256, SMEM_MMA>>>(
        vhf, owh, out_b, out,
        DIMC, DIMC, DIMC, DIMC, 0, 0, 0, 0, 1, 1.0f);
}

// round 15
// speedup vs baseline: 1.0589x; 1.0589x over previous
#include <cuda_runtime.h>
#include <cuda_fp16.h>
#include <math.h>
#include <stdint.h>

// ---------------- problem constants ----------------
#define DIMC   2048
#define NHEADS 2
#define HDIM   1024
#define BATCH  4
#define SEQ    2048
#define M1     (BATCH*SEQ)   // 8192
#define QKVN   (3*DIMC)      // 6144

__device__ __forceinline__ uint32_t smem_u32(const void* p) {
    uint32_t a;
    asm("{ .reg .u64 t; cvta.to.shared.u64 t, %1; cvt.u32.u64 %0, t; }" : "=r"(a) : "l"(p));
    return a;
}

#define CP_ASYNC16(dst, src) \
    asm volatile("cp.async.cg.shared.global [%0], [%1], 16;" :: "r"(dst), "l"(src) : "memory")
#define CP_COMMIT() asm volatile("cp.async.commit_group;" ::: "memory")
#define CP_WAIT2()  asm volatile("cp.async.wait_group 2;" ::: "memory")

#define LDMATRIX_X4(r0, r1, r2, r3, addr) \
    asm volatile("ldmatrix.sync.aligned.m8n8.x4.shared.b16 {%0,%1,%2,%3}, [%4];" \
        : "=r"(r0), "=r"(r1), "=r"(r2), "=r"(r3) : "r"(addr))

#define MMA_F16(c, a, b0, b1) \
    asm volatile("mma.sync.aligned.m16n8k16.row.col.f32.f16.f16.f32 " \
        "{%0,%1,%2,%3}, {%4,%5,%6,%7}, {%8,%9}, {%0,%1,%2,%3};" \
        : "+f"((c)[0]), "+f"((c)[1]), "+f"((c)[2]), "+f"((c)[3]) \
        : "r"((a)[0]), "r"((a)[1]), "r"((a)[2]), "r"((a)[3]), "r"(b0), "r"(b1))

// ---------------- scratch ----------------
__device__ __align__(128) __half g_qkvh[(size_t)M1 * QKVN];   // fp16 qkv
__device__ float g_s  [(size_t)8 * SEQ * SEQ];
__device__ float g_ctab[SEQ * 512];
__device__ float g_stab[SEQ * 512];
__device__ __align__(128) __half g_xf [(size_t)M1*DIMC];
__device__ __align__(128) __half g_wqh[(size_t)QKVN*DIMC];
__device__ __align__(128) __half g_owh[(size_t)DIMC*DIMC];
__device__ __align__(128) __half g_qf [(size_t)8*SEQ*HDIM];
__device__ __align__(128) __half g_kh [(size_t)8*SEQ*HDIM];
__device__ __align__(128) __half g_vth[(size_t)8*HDIM*SEQ];
__device__ __align__(128) __half g_pf [(size_t)8*SEQ*SEQ];
__device__ __align__(128) __half g_vhf[(size_t)M1*DIMC];

// ---------------- RoPE tables (fp32, matches reference dtype math) ----------------
__global__ void rope_tab_kernel() {
    int idx = blockIdx.x * blockDim.x + threadIdx.x;
    int d = idx & 511, l = idx >> 9;
    float inv = expf((float)(2 * d) * (-9.210340371976184f / 1024.0f));
    float th  = (float)l * inv;
    g_ctab[idx] = cosf(th);
    g_stab[idx] = sinf(th);
}

// ---------------- fused fp32 -> fp16 for 3 arrays ----------------
__global__ void conv3_h(const float* __restrict__ a0, __half* __restrict__ o0, int n0,
                        const float* __restrict__ a1, __half* __restrict__ o1, int n1,
                        const float* __restrict__ a2, __half* __restrict__ o2, int n2) {
    int i = blockIdx.x * 256 + threadIdx.x;     // float4 index across all 3 arrays
    const float* src; __half* dst;
    if (i < n0)           { src = a0; dst = o0; }
    else if (i < n0 + n1) { src = a1; dst = o1; i -= n0; }
    else                  { src = a2; dst = o2; i -= n0 + n1; }
    float4 v = ((const float4*)src)[i];
    union { __half b[4]; uint2 u; } H;
    H.b[0] = __float2half_rn(v.x); H.b[1] = __float2half_rn(v.y);
    H.b[2] = __float2half_rn(v.z); H.b[3] = __float2half_rn(v.w);
    ((uint2*)dst)[i] = H.u;
}

// ---------------- fused RoPE + V transpose ----------------
__global__ void rope_vt_fused(const __half* __restrict__ qkvh,
                              __half* __restrict__ qf, __half* __restrict__ kh,
                              float* __restrict__ kout, float* __restrict__ vout,
                              __half* __restrict__ vth) {
    __shared__ __half vt1[32][34], vt2[32][34];
    int z = blockIdx.z;              // b*NHEADS + h
    int b = z >> 1, h = z & 1;
    int l0 = blockIdx.x * 32, d0 = blockIdx.y * 32;   // d0 in [0,512)
    int tx = threadIdx.x, ty = threadIdx.y;

    #pragma unroll
    for (int j = 0; j < 32; j += 8) {
        int l = l0 + ty + j;
        int d = d0 + tx;
        const __half* row = qkvh + (size_t)(b * SEQ + l) * QKVN + h * HDIM;
        float q1 = __half2float(row[d]),            q2 = __half2float(row[d + 512]);
        float k1 = __half2float(row[DIMC + d]),     k2 = __half2float(row[DIMC + d + 512]);
        __half v1 = row[2*DIMC + d],                v2 = row[2*DIMC + d + 512];

        int ti = (l << 9) + d;
        float c = g_ctab[ti], s = g_stab[ti];
        float rq1 = q1*c - q2*s, rq2 = q1*s + q2*c;
        float rk1 = k1*c - k2*s, rk2 = k1*s + k2*c;

        size_t o = (size_t)(z * SEQ + l) * HDIM + d;
        qf[o]        = __float2half_rn(rq1);
        qf[o + 512]  = __float2half_rn(rq2);
        kh[o]        = __float2half_rn(rk1);
        kh[o + 512]  = __float2half_rn(rk2);
        kout[o]       = rk1;
        kout[o + 512] = rk2;
        vout[o]       = __half2float(v1);
        vout[o + 512] = __half2float(v2);

        vt1[tx][ty + j] = v1;   // [d_local][l_local]
        vt2[tx][ty + j] = v2;
    }
    __syncthreads();
    #pragma unroll
    for (int j = 0; j < 32; j += 8) {
        int dl = ty + j;            // d_local
        int l  = l0 + tx;
        vth[((size_t)z * HDIM + d0 + dl)       * SEQ + l] = vt1[dl][tx];
        vth[((size_t)z * HDIM + d0 + 512 + dl) * SEQ + l] = vt2[dl][tx];
    }
}

// ---------------- causal softmax -> fp16 P ----------------
__global__ void softmax_h(const float* __restrict__ S, __half* __restrict__ P) {
    int row = blockIdx.x;
    int l = row & (SEQ - 1);
    const float* p = S + (size_t)row * SEQ;
    int t = threadIdx.x;
    int nproc = (l | 127) + 1;
    bool act = (t * 8) < nproc;

    float v[8];
    float m = -1e30f;
    if (act) {
        float4 v0 = *(const float4*)(p + t * 8);
        float4 v1 = *(const float4*)(p + t * 8 + 4);
        v[0]=v0.x; v[1]=v0.y; v[2]=v0.z; v[3]=v0.w;
        v[4]=v1.x; v[5]=v1.y; v[6]=v1.z; v[7]=v1.w;
        #pragma unroll
        for (int j = 0; j < 8; j++)
            if (t * 8 + j <= l) m = fmaxf(m, v[j]);
    }
    __shared__ float red[256];
    red[t] = m; __syncthreads();
    #pragma unroll
    for (int s = 128; s > 0; s >>= 1) { if (t < s) red[t] = fmaxf(red[t], red[t + s]); __syncthreads(); }
    float mx = red[0]; __syncthreads();

    float sum = 0.f;
    if (act) {
        #pragma unroll
        for (int j = 0; j < 8; j++) {
            v[j] = (t * 8 + j <= l) ? __expf(v[j] - mx) : 0.f;
            sum += v[j];
        }
    }
    red[t] = sum; __syncthreads();
    #pragma unroll
    for (int s = 128; s > 0; s >>= 1) { if (t < s) red[t] += red[t + s]; __syncthreads(); }
    float inv = 1.0f / red[0];

    if (act) {
        union { __half b[8]; uint4 u; } H;
        #pragma unroll
        for (int j = 0; j < 8; j++) H.b[j] = __float2half_rn(v[j] * inv);
        *(uint4*)(P + (size_t)row * SEQ + t * 8) = H.u;
    }
}

// ---------------- warp-MMA fp16 single-pass GEMM (occ 2, 4-stage, 1 sync/chunk) ----------------
// C = alpha*(A@B^T) (+bias). A=[M,K] K-major fp16, B=[N,K] K-major fp16.
// Block 128x128x32, 8 warps (4x2), warp tile 32x64, 4-stage cp.async ring, 2 CTAs/SM.
// CAUSAL: 0 none; 1 scores: skip above diag, index-mask diag; 2 K-limit row0+128, longest-first.
// EPI: 0 -> fp32 C0; 1 -> fp16 C0.
#define KPAD   40
#define MATB   (128 * KPAD * 2)
#define STGB   (2 * MATB)
#define NSTG   4
#define SMEM_MMA (NSTG * STGB)     // 81920 B -> 2 CTAs/SM

__device__ __forceinline__ void load_stage_async(uint32_t sbase,
    const __half* A, const __half* B,
    int lda, int ldb, int row0, int col0, int k0)
{
    const int t = threadIdx.x;
    #pragma unroll
    for (int i = 0; i < 4; i++) {
        int s = t + i * 256;
        int m   = s >> 9;
        int idx = s & 511;
        int row = idx >> 2;
        int c16 = idx & 3;
        int ld  = (m == 0) ? lda : ldb;
        int r0  = (m == 0) ? row0 : col0;
        const __half* src = (m == 0 ? A : B) + (size_t)(r0 + row) * ld + k0 + c16 * 8;
        uint32_t dst = sbase + m * MATB + row * (KPAD * 2) + c16 * 16;
        CP_ASYNC16(dst, src);
    }
}

template<int CAUSAL, int EPI>
__global__ void __launch_bounds__(256, 2) gemm_mma(
    const __half* __restrict__ A, const __half* __restrict__ B,
    const float* __restrict__ bias,
    void* __restrict__ C0,
    int K, int lda, int ldb, int ldc,
    long sA, long sB, long sCo, long sCi, int zdiv, float alpha)
{
    extern __shared__ char smem[];
    const int tid = threadIdx.x;
    const int wid = tid >> 5;
    const int lid = tid & 31;
    const int bz = blockIdx.z;

    // tile coordinates: longest-first for causal-K-limited PV GEMM
    const int row_t = (CAUSAL == 2) ? (gridDim.y - 1 - blockIdx.y) : blockIdx.y;
    const int row0 = row_t * 128;
    const int col0 = blockIdx.x * 128;

    if (CAUSAL == 1 && col0 > row0) return;   // softmax never reads this region

    const size_t zoffC = (size_t)(bz / zdiv) * sCo + (size_t)(bz % zdiv) * sCi;
    A += (size_t)bz * sA;
    B += (size_t)bz * sB;

    int Keff = (CAUSAL == 2) ? min(K, row0 + 128) : K;
    const int nc = Keff >> 5;

    const uint32_t sb = smem_u32(smem);
    const int wm = (wid & 3) * 32;
    const int wn = (wid >> 2) * 64;
    const int lrow = lid & 15;
    const int lcol = (lid >> 4) << 3;

    float acc[2][8][4];
    #pragma unroll
    for (int mt = 0; mt < 2; mt++)
        #pragma unroll
        for (int nt = 0; nt < 8; nt++)
            #pragma unroll
            for (int r = 0; r < 4; r++) acc[mt][nt][r] = 0.f;

    #pragma unroll
    for (int s = 0; s < 3; s++) {
        if (s < nc) load_stage_async(sb + s * STGB, A, B, lda, ldb, row0, col0, s << 5);
        CP_COMMIT();
    }

    for (int c = 0; c < nc; c++) {
        CP_WAIT2();
        __syncthreads();
        if (c + 3 < nc)
            load_stage_async(sb + ((c + 3) & 3) * STGB, A, B,
                             lda, ldb, row0, col0, (c + 3) << 5);
        CP_COMMIT();

        uint32_t stg = sb + (c & 3) * STGB;
        #pragma unroll
        for (int kk = 0; kk < 32; kk += 16) {
            uint32_t af[2][4], bf[4][4];
            #pragma unroll
            for (int mt = 0; mt < 2; mt++) {
                uint32_t ra = stg + ((wm + mt * 16 + lrow) * KPAD + kk + lcol) * 2;
                LDMATRIX_X4(af[mt][0], af[mt][1], af[mt][2], af[mt][3], ra);
            }
            #pragma unroll
            for (int g = 0; g < 4; g++) {
                uint32_t rb = stg + MATB + ((wn + g * 16 + lrow) * KPAD + kk + lcol) * 2;
                LDMATRIX_X4(bf[g][0], bf[g][1], bf[g][2], bf[g][3], rb);
            }
            #pragma unroll
            for (int mt = 0; mt < 2; mt++)
                #pragma unroll
                for (int nt = 0; nt < 8; nt++) {
                    int g = nt >> 1, o = nt & 1;
                    MMA_F16(acc[mt][nt], af[mt], bf[g][o], bf[g][o + 2]);
                }
        }
    }

    // ---------------- epilogue ----------------
    #pragma unroll
    for (int mt = 0; mt < 2; mt++) {
        #pragma unroll
        for (int nt = 0; nt < 8; nt++) {
            int gr0 = row0 + wm + mt * 16 + (lid >> 2);
            int gc  = col0 + wn + nt * 8 + (lid & 3) * 2;
            #pragma unroll
            for (int half = 0; half < 2; half++) {
                int gr = gr0 + half * 8;
                float v0 = acc[mt][nt][2 * half]     * alpha;
                float v1 = acc[mt][nt][2 * half + 1] * alpha;
                if (bias) { v0 += bias[gc]; v1 += bias[gc + 1]; }
                if (CAUSAL == 1 && row0 == col0) {
                    if (gc     > gr) v0 = -1e9f;
                    if (gc + 1 > gr) v1 = -1e9f;
                }
                if (EPI == 0) {
                    float* C = (float*)C0 + zoffC + (size_t)gr * ldc + gc;
                    *(float2*)C = make_float2(v0, v1);
                } else {
                    __half* C = (__half*)C0 + zoffC + (size_t)gr * ldc + gc;
                    union { __half b[2]; uint32_t u; } H;
                    H.b[0] = __float2half_rn(v0);
                    H.b[1] = __float2half_rn(v1);
                    *(uint32_t*)C = H.u;
                }
            }
        }
    }
}

// ---------------- launch ----------------
extern "C" void kernel_launch(void* const* d_in, const int* in_sizes, int n_in,
                              void* d_out, int out_size) {
    const float* x      = (const float*)d_in[0];
    const float* Wqkv_w = (const float*)d_in[2];
    const float* Wqkv_b = (const float*)d_in[3];
    const float* out_w  = (const float*)d_in[4];
    const float* out_b  = (const float*)d_in[5];

    float* out  = (float*)d_out;
    float* kout = out  + (size_t)M1 * DIMC;
    float* vout = kout + (size_t)8 * SEQ * HDIM;

    float *S;
    __half *qkvh,*xf,*wqh,*owh,*qf,*kh,*vth,*pf,*vhf;
    cudaGetSymbolAddress((void**)&qkvh, g_qkvh);
    cudaGetSymbolAddress((void**)&S,    g_s);
    cudaGetSymbolAddress((void**)&xf,   g_xf);
    cudaGetSymbolAddress((void**)&wqh,  g_wqh);
    cudaGetSymbolAddress((void**)&owh,  g_owh);
    cudaGetSymbolAddress((void**)&qf,   g_qf);
    cudaGetSymbolAddress((void**)&kh,   g_kh);
    cudaGetSymbolAddress((void**)&vth,  g_vth);
    cudaGetSymbolAddress((void**)&pf,   g_pf);
    cudaGetSymbolAddress((void**)&vhf,  g_vhf);

    cudaFuncSetAttribute(gemm_mma<0,0>, cudaFuncAttributeMaxDynamicSharedMemorySize, SMEM_MMA);
    cudaFuncSetAttribute(gemm_mma<0,1>, cudaFuncAttributeMaxDynamicSharedMemorySize, SMEM_MMA);
    cudaFuncSetAttribute(gemm_mma<1,0>, cudaFuncAttributeMaxDynamicSharedMemorySize, SMEM_MMA);
    cudaFuncSetAttribute(gemm_mma<2,1>, cudaFuncAttributeMaxDynamicSharedMemorySize, SMEM_MMA);

    // 1) RoPE tables (fp32)
    rope_tab_kernel<<<SEQ, 512>>>();

    // 2) fused conversion of x, Wqkv_w, out_w to fp16 (one launch)
    {
        int n0 = (int)((size_t)M1 * DIMC / 4);
        int n1 = (int)((size_t)QKVN * DIMC / 4);
        int n2 = (int)((size_t)DIMC * DIMC / 4);
        conv3_h<<<(n0 + n1 + n2) / 256, 256>>>(x, xf, n0, Wqkv_w, wqh, n1, out_w, owh, n2);
    }

    // 3) QKV = x @ Wqkv^T + b  -> fp16 qkv  [8192 x 6144 x 2048]
    gemm_mma<0,1><<<dim3(QKVN/128, M1/128, 1), 256, SMEM_MMA>>>(
        xf, wqh, Wqkv_b, qkvh,
        DIMC, DIMC, DIMC, QKVN, 0, 0, 0, 0, 1, 1.0f);

    // 4) fused RoPE + V transpose: qf/kh fp16, kout/vout fp32, vth fp16
    rope_vt_fused<<<dim3(SEQ/32, 512/32, 8), dim3(32, 8)>>>(
        qkvh, qf, kh, kout, vout, vth);

    // 5) S = (1/32) q @ k^T  per head; causal via tile skip + index mask
    gemm_mma<1,0><<<dim3(SEQ/128, SEQ/128, 8), 256, SMEM_MMA>>>(
        qf, kh, nullptr, S,
        HDIM, HDIM, HDIM, SEQ,
        (long)SEQ*HDIM, (long)SEQ*HDIM, (long)SEQ*SEQ, 0, 1, 0.03125f);

    // 6) causal softmax -> fp16 P (zero-fill to PV K-limit)
    softmax_h<<<8 * SEQ, 256>>>(S, pf);

    // 7) VH = P @ V (via Vt), causal K-limit, longest-first; fp16 out to (B,L,D)
    gemm_mma<2,1><<<dim3(HDIM/128, SEQ/128, 8), 256, SMEM_MMA>>>(
        pf, vth, nullptr, vhf,
        SEQ, SEQ, SEQ, DIMC,
        (long)SEQ*SEQ, (long)HDIM*SEQ, (long)SEQ*DIMC, (long)HDIM, NHEADS, 1.0f);

    // 8) out = VH @ out_w^T + out_b  [8192 x 2048 x 2048]
    gemm_mma<0,0><<<dim3(DIMC/128, M1/128, 1), 256, SMEM_MMA>>>(
        vhf, owh, out_b, out,
        DIMC, DIMC, DIMC, DIMC, 0, 0, 0, 0, 1, 1.0f);
}

// round 16
// speedup vs baseline: 1.0629x; 1.0038x over previous
#include <cuda_runtime.h>
#include <cuda_fp16.h>
#include <math.h>
#include <stdint.h>

// ---------------- problem constants ----------------
#define DIMC   2048
#define NHEADS 2
#define HDIM   1024
#define BATCH  4
#define SEQ    2048
#define M1     (BATCH*SEQ)   // 8192
#define QKVN   (3*DIMC)      // 6144

__device__ __forceinline__ uint32_t smem_u32(const void* p) {
    uint32_t a;
    asm("{ .reg .u64 t; cvta.to.shared.u64 t, %1; cvt.u32.u64 %0, t; }" : "=r"(a) : "l"(p));
    return a;
}

#define CP_ASYNC16(dst, src) \
    asm volatile("cp.async.cg.shared.global [%0], [%1], 16;" :: "r"(dst), "l"(src) : "memory")
#define CP_COMMIT() asm volatile("cp.async.commit_group;" ::: "memory")
#define CP_WAIT2()  asm volatile("cp.async.wait_group 2;" ::: "memory")

#define LDMATRIX_X4(r0, r1, r2, r3, addr) \
    asm volatile("ldmatrix.sync.aligned.m8n8.x4.shared.b16 {%0,%1,%2,%3}, [%4];" \
        : "=r"(r0), "=r"(r1), "=r"(r2), "=r"(r3) : "r"(addr))

#define MMA_F16(c, a, b0, b1) \
    asm volatile("mma.sync.aligned.m16n8k16.row.col.f32.f16.f16.f32 " \
        "{%0,%1,%2,%3}, {%4,%5,%6,%7}, {%8,%9}, {%0,%1,%2,%3};" \
        : "+f"((c)[0]), "+f"((c)[1]), "+f"((c)[2]), "+f"((c)[3]) \
        : "r"((a)[0]), "r"((a)[1]), "r"((a)[2]), "r"((a)[3]), "r"(b0), "r"(b1))

// ---------------- scratch ----------------
__device__ __align__(128) __half g_qkvh[(size_t)M1 * QKVN];   // fp16 qkv
__device__ float g_s  [(size_t)8 * SEQ * SEQ];
__device__ float g_ctab[SEQ * 512];
__device__ float g_stab[SEQ * 512];
__device__ __align__(128) __half g_xf [(size_t)M1*DIMC];
__device__ __align__(128) __half g_wqh[(size_t)QKVN*DIMC];
__device__ __align__(128) __half g_owh[(size_t)DIMC*DIMC];
__device__ __align__(128) __half g_qf [(size_t)8*SEQ*HDIM];
__device__ __align__(128) __half g_kh [(size_t)8*SEQ*HDIM];
__device__ __align__(128) __half g_vth[(size_t)8*HDIM*SEQ];
__device__ __align__(128) __half g_pf [(size_t)8*SEQ*SEQ];
__device__ __align__(128) __half g_vhf[(size_t)M1*DIMC];

// ---------------- RoPE tables (fp32, matches reference dtype math) ----------------
__global__ void rope_tab_kernel() {
    int idx = blockIdx.x * blockDim.x + threadIdx.x;
    int d = idx & 511, l = idx >> 9;
    float inv = expf((float)(2 * d) * (-9.210340371976184f / 1024.0f));
    float th  = (float)l * inv;
    g_ctab[idx] = cosf(th);
    g_stab[idx] = sinf(th);
}

// ---------------- fused fp32 -> fp16 for 3 arrays ----------------
__global__ void conv3_h(const float* __restrict__ a0, __half* __restrict__ o0, int n0,
                        const float* __restrict__ a1, __half* __restrict__ o1, int n1,
                        const float* __restrict__ a2, __half* __restrict__ o2, int n2) {
    int i = blockIdx.x * 256 + threadIdx.x;     // float4 index across all 3 arrays
    const float* src; __half* dst;
    if (i < n0)           { src = a0; dst = o0; }
    else if (i < n0 + n1) { src = a1; dst = o1; i -= n0; }
    else                  { src = a2; dst = o2; i -= n0 + n1; }
    float4 v = ((const float4*)src)[i];
    union { __half b[4]; uint2 u; } H;
    H.b[0] = __float2half_rn(v.x); H.b[1] = __float2half_rn(v.y);
    H.b[2] = __float2half_rn(v.z); H.b[3] = __float2half_rn(v.w);
    ((uint2*)dst)[i] = H.u;
}

// ---------------- fused RoPE + V transpose (vectorized half2/float2) ----------------
// Block (32,8): 32 l-rows x 64 d-cols (d-pairs via half2), d0 in [0,512), pairs with d+512.
__global__ void rope_vt_fused(const __half* __restrict__ qkvh,
                              __half* __restrict__ qf, __half* __restrict__ kh,
                              float* __restrict__ kout, float* __restrict__ vout,
                              __half* __restrict__ vth) {
    __shared__ __half vt1[64][34], vt2[64][34];
    int z = blockIdx.z;              // b*NHEADS + h
    int b = z >> 1, h = z & 1;
    int l0 = blockIdx.x * 32, d0 = blockIdx.y * 64;
    int tx = threadIdx.x, ty = threadIdx.y;
    int d = d0 + 2 * tx;

    #pragma unroll
    for (int j = 0; j < 32; j += 8) {
        int l = l0 + ty + j;
        const __half* row = qkvh + (size_t)(b * SEQ + l) * QKVN + h * HDIM;
        __half2 q1 = *(const __half2*)(row + d);
        __half2 q2 = *(const __half2*)(row + d + 512);
        __half2 k1 = *(const __half2*)(row + DIMC + d);
        __half2 k2 = *(const __half2*)(row + DIMC + d + 512);
        __half2 v1 = *(const __half2*)(row + 2*DIMC + d);
        __half2 v2 = *(const __half2*)(row + 2*DIMC + d + 512);

        int ti = (l << 9) + d;
        float2 c = *(const float2*)(g_ctab + ti);
        float2 s = *(const float2*)(g_stab + ti);

        float2 q1f = __half22float2(q1), q2f = __half22float2(q2);
        float2 k1f = __half22float2(k1), k2f = __half22float2(k2);

        float rq1x = q1f.x*c.x - q2f.x*s.x, rq1y = q1f.y*c.y - q2f.y*s.y;
        float rq2x = q1f.x*s.x + q2f.x*c.x, rq2y = q1f.y*s.y + q2f.y*c.y;
        float rk1x = k1f.x*c.x - k2f.x*s.x, rk1y = k1f.y*c.y - k2f.y*s.y;
        float rk2x = k1f.x*s.x + k2f.x*c.x, rk2y = k1f.y*s.y + k2f.y*c.y;

        size_t o = (size_t)(z * SEQ + l) * HDIM + d;
        *(__half2*)(qf + o)       = __floats2half2_rn(rq1x, rq1y);
        *(__half2*)(qf + o + 512) = __floats2half2_rn(rq2x, rq2y);
        *(__half2*)(kh + o)       = __floats2half2_rn(rk1x, rk1y);
        *(__half2*)(kh + o + 512) = __floats2half2_rn(rk2x, rk2y);
        *(float2*)(kout + o)       = make_float2(rk1x, rk1y);
        *(float2*)(kout + o + 512) = make_float2(rk2x, rk2y);
        *(float2*)(vout + o)       = __half22float2(v1);
        *(float2*)(vout + o + 512) = __half22float2(v2);

        int ll = ty + j;
        vt1[2*tx][ll]     = __low2half(v1);
        vt1[2*tx + 1][ll] = __high2half(v1);
        vt2[2*tx][ll]     = __low2half(v2);
        vt2[2*tx + 1][ll] = __high2half(v2);
    }
    __syncthreads();

    // transposed write: 64 dl x 16 l-pairs = 1024 half2 stores per tile, 256 threads
    int tid = ty * 32 + tx;
    #pragma unroll
    for (int it = 0; it < 4; it++) {
        int idx = tid + it * 256;
        int dl = idx >> 4;          // 0..63
        int lp = idx & 15;          // l-pair index
        __half2 a  = __halves2half2(vt1[dl][2*lp], vt1[dl][2*lp + 1]);
        __half2 bb = __halves2half2(vt2[dl][2*lp], vt2[dl][2*lp + 1]);
        size_t ob = ((size_t)z * HDIM + d0 + dl) * SEQ + l0 + 2*lp;
        *(__half2*)(vth + ob)                      = a;
        *(__half2*)(vth + ob + (size_t)512 * SEQ)  = bb;
    }
}

// ---------------- causal softmax -> fp16 P ----------------
__global__ void softmax_h(const float* __restrict__ S, __half* __restrict__ P) {
    int row = blockIdx.x;
    int l = row & (SEQ - 1);
    const float* p = S + (size_t)row * SEQ;
    int t = threadIdx.x;
    int nproc = (l | 127) + 1;
    bool act = (t * 8) < nproc;

    float v[8];
    float m = -1e30f;
    if (act) {
        float4 v0 = *(const float4*)(p + t * 8);
        float4 v1 = *(const float4*)(p + t * 8 + 4);
        v[0]=v0.x; v[1]=v0.y; v[2]=v0.z; v[3]=v0.w;
        v[4]=v1.x; v[5]=v1.y; v[6]=v1.z; v[7]=v1.w;
        #pragma unroll
        for (int j = 0; j < 8; j++)
            if (t * 8 + j <= l) m = fmaxf(m, v[j]);
    }
    __shared__ float red[256];
    red[t] = m; __syncthreads();
    #pragma unroll
    for (int s = 128; s > 0; s >>= 1) { if (t < s) red[t] = fmaxf(red[t], red[t + s]); __syncthreads(); }
    float mx = red[0]; __syncthreads();

    float sum = 0.f;
    if (act) {
        #pragma unroll
        for (int j = 0; j < 8; j++) {
            v[j] = (t * 8 + j <= l) ? __expf(v[j] - mx) : 0.f;
            sum += v[j];
        }
    }
    red[t] = sum; __syncthreads();
    #pragma unroll
    for (int s = 128; s > 0; s >>= 1) { if (t < s) red[t] += red[t + s]; __syncthreads(); }
    float inv = 1.0f / red[0];

    if (act) {
        union { __half b[8]; uint4 u; } H;
        #pragma unroll
        for (int j = 0; j < 8; j++) H.b[j] = __float2half_rn(v[j] * inv);
        *(uint4*)(P + (size_t)row * SEQ + t * 8) = H.u;
    }
}

// ---------------- warp-MMA fp16 single-pass GEMM (occ 2, 4-stage, 1 sync/chunk) ----------------
// C = alpha*(A@B^T) (+bias). A=[M,K] K-major fp16, B=[N,K] K-major fp16.
// Block 128x128x32, 8 warps (4x2), warp tile 32x64, 4-stage cp.async ring, 2 CTAs/SM.
// CAUSAL: 0 none; 1 scores: skip above diag, index-mask diag; 2 K-limit row0+128, longest-first.
// EPI: 0 -> fp32 C0; 1 -> fp16 C0.
#define KPAD   40
#define MATB   (128 * KPAD * 2)
#define STGB   (2 * MATB)
#define NSTG   4
#define SMEM_MMA (NSTG * STGB)     // 81920 B -> 2 CTAs/SM

__device__ __forceinline__ void load_stage_async(uint32_t sbase,
    const __half* A, const __half* B,
    int lda, int ldb, int row0, int col0, int k0)
{
    const int t = threadIdx.x;
    #pragma unroll
    for (int i = 0; i < 4; i++) {
        int s = t + i * 256;
        int m   = s >> 9;
        int idx = s & 511;
        int row = idx >> 2;
        int c16 = idx & 3;
        int ld  = (m == 0) ? lda : ldb;
        int r0  = (m == 0) ? row0 : col0;
        const __half* src = (m == 0 ? A : B) + (size_t)(r0 + row) * ld + k0 + c16 * 8;
        uint32_t dst = sbase + m * MATB + row * (KPAD * 2) + c16 * 16;
        CP_ASYNC16(dst, src);
    }
}

template<int CAUSAL, int EPI>
__global__ void __launch_bounds__(256, 2) gemm_mma(
    const __half* __restrict__ A, const __half* __restrict__ B,
    const float* __restrict__ bias,
    void* __restrict__ C0,
    int K, int lda, int ldb, int ldc,
    long sA, long sB, long sCo, long sCi, int zdiv, float alpha)
{
    extern __shared__ char smem[];
    const int tid = threadIdx.x;
    const int wid = tid >> 5;
    const int lid = tid & 31;
    const int bz = blockIdx.z;

    const int row_t = (CAUSAL == 2) ? (gridDim.y - 1 - blockIdx.y) : blockIdx.y;
    const int row0 = row_t * 128;
    const int col0 = blockIdx.x * 128;

    if (CAUSAL == 1 && col0 > row0) return;   // softmax never reads this region

    const size_t zoffC = (size_t)(bz / zdiv) * sCo + (size_t)(bz % zdiv) * sCi;
    A += (size_t)bz * sA;
    B += (size_t)bz * sB;

    int Keff = (CAUSAL == 2) ? min(K, row0 + 128) : K;
    const int nc = Keff >> 5;

    const uint32_t sb = smem_u32(smem);
    const int wm = (wid & 3) * 32;
    const int wn = (wid >> 2) * 64;
    const int lrow = lid & 15;
    const int lcol = (lid >> 4) << 3;

    float acc[2][8][4];
    #pragma unroll
    for (int mt = 0; mt < 2; mt++)
        #pragma unroll
        for (int nt = 0; nt < 8; nt++)
            #pragma unroll
            for (int r = 0; r < 4; r++) acc[mt][nt][r] = 0.f;

    #pragma unroll
    for (int s = 0; s < 3; s++) {
        if (s < nc) load_stage_async(sb + s * STGB, A, B, lda, ldb, row0, col0, s << 5);
        CP_COMMIT();
    }

    for (int c = 0; c < nc; c++) {
        CP_WAIT2();
        __syncthreads();
        if (c + 3 < nc)
            load_stage_async(sb + ((c + 3) & 3) * STGB, A, B,
                             lda, ldb, row0, col0, (c + 3) << 5);
        CP_COMMIT();

        uint32_t stg = sb + (c & 3) * STGB;
        #pragma unroll
        for (int kk = 0; kk < 32; kk += 16) {
            uint32_t af[2][4], bf[4][4];
            #pragma unroll
            for (int mt = 0; mt < 2; mt++) {
                uint32_t ra = stg + ((wm + mt * 16 + lrow) * KPAD + kk + lcol) * 2;
                LDMATRIX_X4(af[mt][0], af[mt][1], af[mt][2], af[mt][3], ra);
            }
            #pragma unroll
            for (int g = 0; g < 4; g++) {
                uint32_t rb = stg + MATB + ((wn + g * 16 + lrow) * KPAD + kk + lcol) * 2;
                LDMATRIX_X4(bf[g][0], bf[g][1], bf[g][2], bf[g][3], rb);
            }
            #pragma unroll
            for (int mt = 0; mt < 2; mt++)
                #pragma unroll
                for (int nt = 0; nt < 8; nt++) {
                    int g = nt >> 1, o = nt & 1;
                    MMA_F16(acc[mt][nt], af[mt], bf[g][o], bf[g][o + 2]);
                }
        }
    }

    // ---------------- epilogue ----------------
    #pragma unroll
    for (int mt = 0; mt < 2; mt++) {
        #pragma unroll
        for (int nt = 0; nt < 8; nt++) {
            int gr0 = row0 + wm + mt * 16 + (lid >> 2);
            int gc  = col0 + wn + nt * 8 + (lid & 3) * 2;
            #pragma unroll
            for (int half = 0; half < 2; half++) {
                int gr = gr0 + half * 8;
                float v0 = acc[mt][nt][2 * half]     * alpha;
                float v1 = acc[mt][nt][2 * half + 1] * alpha;
                if (bias) { v0 += bias[gc]; v1 += bias[gc + 1]; }
                if (CAUSAL == 1 && row0 == col0) {
                    if (gc     > gr) v0 = -1e9f;
                    if (gc + 1 > gr) v1 = -1e9f;
                }
                if (EPI == 0) {
                    float* C = (float*)C0 + zoffC + (size_t)gr * ldc + gc;
                    *(float2*)C = make_float2(v0, v1);
                } else {
                    __half* C = (__half*)C0 + zoffC + (size_t)gr * ldc + gc;
                    union { __half b[2]; uint32_t u; } H;
                    H.b[0] = __float2half_rn(v0);
                    H.b[1] = __float2half_rn(v1);
                    *(uint32_t*)C = H.u;
                }
            }
        }
    }
}

// ---------------- launch ----------------
extern "C" void kernel_launch(void* const* d_in, const int* in_sizes, int n_in,
                              void* d_out, int out_size) {
    const float* x      = (const float*)d_in[0];
    const float* Wqkv_w = (const float*)d_in[2];
    const float* Wqkv_b = (const float*)d_in[3];
    const float* out_w  = (const float*)d_in[4];
    const float* out_b  = (const float*)d_in[5];

    float* out  = (float*)d_out;
    float* kout = out  + (size_t)M1 * DIMC;
    float* vout = kout + (size_t)8 * SEQ * HDIM;

    float *S;
    __half *qkvh,*xf,*wqh,*owh,*qf,*kh,*vth,*pf,*vhf;
    cudaGetSymbolAddress((void**)&qkvh, g_qkvh);
    cudaGetSymbolAddress((void**)&S,    g_s);
    cudaGetSymbolAddress((void**)&xf,   g_xf);
    cudaGetSymbolAddress((void**)&wqh,  g_wqh);
    cudaGetSymbolAddress((void**)&owh,  g_owh);
    cudaGetSymbolAddress((void**)&qf,   g_qf);
    cudaGetSymbolAddress((void**)&kh,   g_kh);
    cudaGetSymbolAddress((void**)&vth,  g_vth);
    cudaGetSymbolAddress((void**)&pf,   g_pf);
    cudaGetSymbolAddress((void**)&vhf,  g_vhf);

    cudaFuncSetAttribute(gemm_mma<0,0>, cudaFuncAttributeMaxDynamicSharedMemorySize, SMEM_MMA);
    cudaFuncSetAttribute(gemm_mma<0,1>, cudaFuncAttributeMaxDynamicSharedMemorySize, SMEM_MMA);
    cudaFuncSetAttribute(gemm_mma<1,0>, cudaFuncAttributeMaxDynamicSharedMemorySize, SMEM_MMA);
    cudaFuncSetAttribute(gemm_mma<2,1>, cudaFuncAttributeMaxDynamicSharedMemorySize, SMEM_MMA);

    // 1) RoPE tables (fp32)
    rope_tab_kernel<<<SEQ, 512>>>();

    // 2) fused conversion of x, Wqkv_w, out_w to fp16 (one launch)
    {
        int n0 = (int)((size_t)M1 * DIMC / 4);
        int n1 = (int)((size_t)QKVN * DIMC / 4);
        int n2 = (int)((size_t)DIMC * DIMC / 4);
        conv3_h<<<(n0 + n1 + n2) / 256, 256>>>(x, xf, n0, Wqkv_w, wqh, n1, out_w, owh, n2);
    }

    // 3) QKV = x @ Wqkv^T + b  -> fp16 qkv  [8192 x 6144 x 2048]
    gemm_mma<0,1><<<dim3(QKVN/128, M1/128, 1), 256, SMEM_MMA>>>(
        xf, wqh, Wqkv_b, qkvh,
        DIMC, DIMC, DIMC, QKVN, 0, 0, 0, 0, 1, 1.0f);

    // 4) fused RoPE + V transpose (vectorized): qf/kh fp16, kout/vout fp32, vth fp16
    rope_vt_fused<<<dim3(SEQ/32, 512/64, 8), dim3(32, 8)>>>(
        qkvh, qf, kh, kout, vout, vth);

    // 5) S = (1/32) q @ k^T  per head; causal via tile skip + index mask
    gemm_mma<1,0><<<dim3(SEQ/128, SEQ/128, 8), 256, SMEM_MMA>>>(
        qf, kh, nullptr, S,
        HDIM, HDIM, HDIM, SEQ,
        (long)SEQ*HDIM, (long)SEQ*HDIM, (long)SEQ*SEQ, 0, 1, 0.03125f);

    // 6) causal softmax -> fp16 P (zero-fill to PV K-limit)
    softmax_h<<<8 * SEQ, 256>>>(S, pf);

    // 7) VH = P @ V (via Vt), causal K-limit, longest-first; fp16 out to (B,L,D)
    gemm_mma<2,1><<<dim3(HDIM/128, SEQ/128, 8), 256, SMEM_MMA>>>(
        pf, vth, nullptr, vhf,
        SEQ, SEQ, SEQ, DIMC,
        (long)SEQ*SEQ, (long)HDIM*SEQ, (long)SEQ*DIMC, (long)HDIM, NHEADS, 1.0f);

    // 8) out = VH @ out_w^T + out_b  [8192 x 2048 x 2048]
    gemm_mma<0,0><<<dim3(DIMC/128, M1/128, 1), 256, SMEM_MMA>>>(
        vhf, owh, out_b, out,
        DIMC, DIMC, DIMC, DIMC, 0, 0, 0, 0, 1, 1.0f);
}

// round 17
// speedup vs baseline: 1.0643x; 1.0013x over previous
#include <cuda_runtime.h>
#include <cuda_fp16.h>
#include <math.h>
#include <stdint.h>

// ---------------- problem constants ----------------
#define DIMC   2048
#define NHEADS 2
#define HDIM   1024
#define BATCH  4
#define SEQ    2048
#define M1     (BATCH*SEQ)   // 8192
#define QKVN   (3*DIMC)      // 6144

__device__ __forceinline__ uint32_t smem_u32(const void* p) {
    uint32_t a;
    asm("{ .reg .u64 t; cvta.to.shared.u64 t, %1; cvt.u32.u64 %0, t; }" : "=r"(a) : "l"(p));
    return a;
}

#define CP_ASYNC16(dst, src) \
    asm volatile("cp.async.cg.shared.global [%0], [%1], 16;" :: "r"(dst), "l"(src) : "memory")
#define CP_COMMIT() asm volatile("cp.async.commit_group;" ::: "memory")
#define CP_WAIT3()  asm volatile("cp.async.wait_group 3;" ::: "memory")

#define LDMATRIX_X4(r0, r1, r2, r3, addr) \
    asm volatile("ldmatrix.sync.aligned.m8n8.x4.shared.b16 {%0,%1,%2,%3}, [%4];" \
        : "=r"(r0), "=r"(r1), "=r"(r2), "=r"(r3) : "r"(addr))

#define MMA_F16(c, a, b0, b1) \
    asm volatile("mma.sync.aligned.m16n8k16.row.col.f32.f16.f16.f32 " \
        "{%0,%1,%2,%3}, {%4,%5,%6,%7}, {%8,%9}, {%0,%1,%2,%3};" \
        : "+f"((c)[0]), "+f"((c)[1]), "+f"((c)[2]), "+f"((c)[3]) \
        : "r"((a)[0]), "r"((a)[1]), "r"((a)[2]), "r"((a)[3]), "r"(b0), "r"(b1))

// ---------------- scratch ----------------
__device__ __align__(128) __half g_qkvh[(size_t)M1 * QKVN];   // fp16 qkv
__device__ float g_s  [(size_t)8 * SEQ * SEQ];
__device__ float g_ctab[SEQ * 512];
__device__ float g_stab[SEQ * 512];
__device__ __align__(128) __half g_xf [(size_t)M1*DIMC];
__device__ __align__(128) __half g_wqh[(size_t)QKVN*DIMC];
__device__ __align__(128) __half g_owh[(size_t)DIMC*DIMC];
__device__ __align__(128) __half g_qf [(size_t)8*SEQ*HDIM];
__device__ __align__(128) __half g_kh [(size_t)8*SEQ*HDIM];
__device__ __align__(128) __half g_vth[(size_t)8*HDIM*SEQ];
__device__ __align__(128) __half g_pf [(size_t)8*SEQ*SEQ];
__device__ __align__(128) __half g_vhf[(size_t)M1*DIMC];

// ---------------- fused: fp32->fp16 for 3 arrays + RoPE tables (one launch) ----------------
// blocks [0, nconv): conversion; blocks [nconv, nconv + SEQ*512/256): tables.
__global__ void conv3_tab(const float* __restrict__ a0, __half* __restrict__ o0, int n0,
                          const float* __restrict__ a1, __half* __restrict__ o1, int n1,
                          const float* __restrict__ a2, __half* __restrict__ o2, int n2,
                          int nconv) {
    if ((int)blockIdx.x >= nconv) {
        int idx = (blockIdx.x - nconv) * 256 + threadIdx.x;   // l*512 + d
        int d = idx & 511, l = idx >> 9;
        float inv = expf((float)(2 * d) * (-9.210340371976184f / 1024.0f));
        float th  = (float)l * inv;
        g_ctab[idx] = cosf(th);
        g_stab[idx] = sinf(th);
        return;
    }
    int i = blockIdx.x * 256 + threadIdx.x;
    const float* src; __half* dst;
    if (i < n0)           { src = a0; dst = o0; }
    else if (i < n0 + n1) { src = a1; dst = o1; i -= n0; }
    else                  { src = a2; dst = o2; i -= n0 + n1; }
    float4 v = ((const float4*)src)[i];
    union { __half b[4]; uint2 u; } H;
    H.b[0] = __float2half_rn(v.x); H.b[1] = __float2half_rn(v.y);
    H.b[2] = __float2half_rn(v.z); H.b[3] = __float2half_rn(v.w);
    ((uint2*)dst)[i] = H.u;
}

// ---------------- fused RoPE + V transpose (vectorized half2/float2) ----------------
__global__ void rope_vt_fused(const __half* __restrict__ qkvh,
                              __half* __restrict__ qf, __half* __restrict__ kh,
                              float* __restrict__ kout, float* __restrict__ vout,
                              __half* __restrict__ vth) {
    __shared__ __half vt1[64][34], vt2[64][34];
    int z = blockIdx.z;              // b*NHEADS + h
    int b = z >> 1, h = z & 1;
    int l0 = blockIdx.x * 32, d0 = blockIdx.y * 64;
    int tx = threadIdx.x, ty = threadIdx.y;
    int d = d0 + 2 * tx;

    #pragma unroll
    for (int j = 0; j < 32; j += 8) {
        int l = l0 + ty + j;
        const __half* row = qkvh + (size_t)(b * SEQ + l) * QKVN + h * HDIM;
        __half2 q1 = *(const __half2*)(row + d);
        __half2 q2 = *(const __half2*)(row + d + 512);
        __half2 k1 = *(const __half2*)(row + DIMC + d);
        __half2 k2 = *(const __half2*)(row + DIMC + d + 512);
        __half2 v1 = *(const __half2*)(row + 2*DIMC + d);
        __half2 v2 = *(const __half2*)(row + 2*DIMC + d + 512);

        int ti = (l << 9) + d;
        float2 c = *(const float2*)(g_ctab + ti);
        float2 s = *(const float2*)(g_stab + ti);

        float2 q1f = __half22float2(q1), q2f = __half22float2(q2);
        float2 k1f = __half22float2(k1), k2f = __half22float2(k2);

        float rq1x = q1f.x*c.x - q2f.x*s.x, rq1y = q1f.y*c.y - q2f.y*s.y;
        float rq2x = q1f.x*s.x + q2f.x*c.x, rq2y = q1f.y*s.y + q2f.y*c.y;
        float rk1x = k1f.x*c.x - k2f.x*s.x, rk1y = k1f.y*c.y - k2f.y*s.y;
        float rk2x = k1f.x*s.x + k2f.x*c.x, rk2y = k1f.y*s.y + k2f.y*c.y;

        size_t o = (size_t)(z * SEQ + l) * HDIM + d;
        *(__half2*)(qf + o)       = __floats2half2_rn(rq1x, rq1y);
        *(__half2*)(qf + o + 512) = __floats2half2_rn(rq2x, rq2y);
        *(__half2*)(kh + o)       = __floats2half2_rn(rk1x, rk1y);
        *(__half2*)(kh + o + 512) = __floats2half2_rn(rk2x, rk2y);
        *(float2*)(kout + o)       = make_float2(rk1x, rk1y);
        *(float2*)(kout + o + 512) = make_float2(rk2x, rk2y);
        *(float2*)(vout + o)       = __half22float2(v1);
        *(float2*)(vout + o + 512) = __half22float2(v2);

        int ll = ty + j;
        vt1[2*tx][ll]     = __low2half(v1);
        vt1[2*tx + 1][ll] = __high2half(v1);
        vt2[2*tx][ll]     = __low2half(v2);
        vt2[2*tx + 1][ll] = __high2half(v2);
    }
    __syncthreads();

    int tid = ty * 32 + tx;
    #pragma unroll
    for (int it = 0; it < 4; it++) {
        int idx = tid + it * 256;
        int dl = idx >> 4;
        int lp = idx & 15;
        __half2 a  = __halves2half2(vt1[dl][2*lp], vt1[dl][2*lp + 1]);
        __half2 bb = __halves2half2(vt2[dl][2*lp], vt2[dl][2*lp + 1]);
        size_t ob = ((size_t)z * HDIM + d0 + dl) * SEQ + l0 + 2*lp;
        *(__half2*)(vth + ob)                      = a;
        *(__half2*)(vth + ob + (size_t)512 * SEQ)  = bb;
    }
}

// ---------------- causal softmax -> fp16 P ----------------
__global__ void softmax_h(const float* __restrict__ S, __half* __restrict__ P) {
    int row = blockIdx.x;
    int l = row & (SEQ - 1);
    const float* p = S + (size_t)row * SEQ;
    int t = threadIdx.x;
    int nproc = (l | 127) + 1;
    bool act = (t * 8) < nproc;

    float v[8];
    float m = -1e30f;
    if (act) {
        float4 v0 = *(const float4*)(p + t * 8);
        float4 v1 = *(const float4*)(p + t * 8 + 4);
        v[0]=v0.x; v[1]=v0.y; v[2]=v0.z; v[3]=v0.w;
        v[4]=v1.x; v[5]=v1.y; v[6]=v1.z; v[7]=v1.w;
        #pragma unroll
        for (int j = 0; j < 8; j++)
            if (t * 8 + j <= l) m = fmaxf(m, v[j]);
    }
    __shared__ float red[256];
    red[t] = m; __syncthreads();
    #pragma unroll
    for (int s = 128; s > 0; s >>= 1) { if (t < s) red[t] = fmaxf(red[t], red[t + s]); __syncthreads(); }
    float mx = red[0]; __syncthreads();

    float sum = 0.f;
    if (act) {
        #pragma unroll
        for (int j = 0; j < 8; j++) {
            v[j] = (t * 8 + j <= l) ? __expf(v[j] - mx) : 0.f;
            sum += v[j];
        }
    }
    red[t] = sum; __syncthreads();
    #pragma unroll
    for (int s = 128; s > 0; s >>= 1) { if (t < s) red[t] += red[t + s]; __syncthreads(); }
    float inv = 1.0f / red[0];

    if (act) {
        union { __half b[8]; uint4 u; } H;
        #pragma unroll
        for (int j = 0; j < 8; j++) H.b[j] = __float2half_rn(v[j] * inv);
        *(uint4*)(P + (size_t)row * SEQ + t * 8) = H.u;
    }
}

// ---------------- warp-MMA fp16 single-pass GEMM (occ 2, 5-stage, 1 sync/chunk) ----------------
// C = alpha*(A@B^T) (+bias). A=[M,K] K-major fp16, B=[N,K] K-major fp16.
// Block 128x128x32, 8 warps (4x2), warp tile 32x64, 5-stage cp.async ring, 2 CTAs/SM.
// CAUSAL: 0 none; 1 scores: skip above diag, index-mask diag; 2 K-limit row0+128, longest-first.
// EPI: 0 -> fp32 C0; 1 -> fp16 C0.
#define KPAD   40
#define MATB   (128 * KPAD * 2)
#define STGB   (2 * MATB)
#define NSTG   5
#define SMEM_MMA (NSTG * STGB)     // 102400 B -> target 2 CTAs/SM (204.8 KB)

__device__ __forceinline__ void load_stage_async(uint32_t sbase,
    const __half* A, const __half* B,
    int lda, int ldb, int row0, int col0, int k0)
{
    const int t = threadIdx.x;
    #pragma unroll
    for (int i = 0; i < 4; i++) {
        int s = t + i * 256;
        int m   = s >> 9;
        int idx = s & 511;
        int row = idx >> 2;
        int c16 = idx & 3;
        int ld  = (m == 0) ? lda : ldb;
        int r0  = (m == 0) ? row0 : col0;
        const __half* src = (m == 0 ? A : B) + (size_t)(r0 + row) * ld + k0 + c16 * 8;
        uint32_t dst = sbase + m * MATB + row * (KPAD * 2) + c16 * 16;
        CP_ASYNC16(dst, src);
    }
}

template<int CAUSAL, int EPI>
__global__ void __launch_bounds__(256, 2) gemm_mma(
    const __half* __restrict__ A, const __half* __restrict__ B,
    const float* __restrict__ bias,
    void* __restrict__ C0,
    int K, int lda, int ldb, int ldc,
    long sA, long sB, long sCo, long sCi, int zdiv, float alpha)
{
    extern __shared__ char smem[];
    const int tid = threadIdx.x;
    const int wid = tid >> 5;
    const int lid = tid & 31;
    const int bz = blockIdx.z;

    const int row_t = (CAUSAL == 2) ? (gridDim.y - 1 - blockIdx.y) : blockIdx.y;
    const int row0 = row_t * 128;
    const int col0 = blockIdx.x * 128;

    if (CAUSAL == 1 && col0 > row0) return;   // softmax never reads this region

    const size_t zoffC = (size_t)(bz / zdiv) * sCo + (size_t)(bz % zdiv) * sCi;
    A += (size_t)bz * sA;
    B += (size_t)bz * sB;

    int Keff = (CAUSAL == 2) ? min(K, row0 + 128) : K;
    const int nc = Keff >> 5;

    const uint32_t sb = smem_u32(smem);
    const int wm = (wid & 3) * 32;
    const int wn = (wid >> 2) * 64;
    const int lrow = lid & 15;
    const int lcol = (lid >> 4) << 3;

    float acc[2][8][4];
    #pragma unroll
    for (int mt = 0; mt < 2; mt++)
        #pragma unroll
        for (int nt = 0; nt < 8; nt++)
            #pragma unroll
            for (int r = 0; r < 4; r++) acc[mt][nt][r] = 0.f;

    // prologue: 4 stages in flight (uniform 4 commits)
    int stg_i = 0;
    #pragma unroll
    for (int s = 0; s < 4; s++) {
        if (s < nc) load_stage_async(sb + s * STGB, A, B, lda, ldb, row0, col0, s << 5);
        CP_COMMIT();
    }

    for (int c = 0; c < nc; c++) {
        CP_WAIT3();              // stage c complete (3 newest groups may be in flight)
        __syncthreads();         // single barrier per chunk
        if (c + 4 < nc) {
            int ps = c + 4;
            int slot = ps % NSTG;
            load_stage_async(sb + slot * STGB, A, B, lda, ldb, row0, col0, ps << 5);
        }
        CP_COMMIT();

        uint32_t stg = sb + stg_i * STGB;
        stg_i = (stg_i + 1 == NSTG) ? 0 : stg_i + 1;
        #pragma unroll
        for (int kk = 0; kk < 32; kk += 16) {
            uint32_t af[2][4], bf[4][4];
            #pragma unroll
            for (int mt = 0; mt < 2; mt++) {
                uint32_t ra = stg + ((wm + mt * 16 + lrow) * KPAD + kk + lcol) * 2;
                LDMATRIX_X4(af[mt][0], af[mt][1], af[mt][2], af[mt][3], ra);
            }
            #pragma unroll
            for (int g = 0; g < 4; g++) {
                uint32_t rb = stg + MATB + ((wn + g * 16 + lrow) * KPAD + kk + lcol) * 2;
                LDMATRIX_X4(bf[g][0], bf[g][1], bf[g][2], bf[g][3], rb);
            }
            #pragma unroll
            for (int mt = 0; mt < 2; mt++)
                #pragma unroll
                for (int nt = 0; nt < 8; nt++) {
                    int g = nt >> 1, o = nt & 1;
                    MMA_F16(acc[mt][nt], af[mt], bf[g][o], bf[g][o + 2]);
                }
        }
    }

    // ---------------- epilogue ----------------
    #pragma unroll
    for (int mt = 0; mt < 2; mt++) {
        #pragma unroll
        for (int nt = 0; nt < 8; nt++) {
            int gr0 = row0 + wm + mt * 16 + (lid >> 2);
            int gc  = col0 + wn + nt * 8 + (lid & 3) * 2;
            #pragma unroll
            for (int half = 0; half < 2; half++) {
                int gr = gr0 + half * 8;
                float v0 = acc[mt][nt][2 * half]     * alpha;
                float v1 = acc[mt][nt][2 * half + 1] * alpha;
                if (bias) { v0 += bias[gc]; v1 += bias[gc + 1]; }
                if (CAUSAL == 1 && row0 == col0) {
                    if (gc     > gr) v0 = -1e9f;
                    if (gc + 1 > gr) v1 = -1e9f;
                }
                if (EPI == 0) {
                    float* C = (float*)C0 + zoffC + (size_t)gr * ldc + gc;
                    *(float2*)C = make_float2(v0, v1);
                } else {
                    __half* C = (__half*)C0 + zoffC + (size_t)gr * ldc + gc;
                    union { __half b[2]; uint32_t u; } H;
                    H.b[0] = __float2half_rn(v0);
                    H.b[1] = __float2half_rn(v1);
                    *(uint32_t*)C = H.u;
                }
            }
        }
    }
}

// ---------------- launch ----------------
extern "C" void kernel_launch(void* const* d_in, const int* in_sizes, int n_in,
                              void* d_out, int out_size) {
    const float* x      = (const float*)d_in[0];
    const float* Wqkv_w = (const float*)d_in[2];
    const float* Wqkv_b = (const float*)d_in[3];
    const float* out_w  = (const float*)d_in[4];
    const float* out_b  = (const float*)d_in[5];

    float* out  = (float*)d_out;
    float* kout = out  + (size_t)M1 * DIMC;
    float* vout = kout + (size_t)8 * SEQ * HDIM;

    float *S;
    __half *qkvh,*xf,*wqh,*owh,*qf,*kh,*vth,*pf,*vhf;
    cudaGetSymbolAddress((void**)&qkvh, g_qkvh);
    cudaGetSymbolAddress((void**)&S,    g_s);
    cudaGetSymbolAddress((void**)&xf,   g_xf);
    cudaGetSymbolAddress((void**)&wqh,  g_wqh);
    cudaGetSymbolAddress((void**)&owh,  g_owh);
    cudaGetSymbolAddress((void**)&qf,   g_qf);
    cudaGetSymbolAddress((void**)&kh,   g_kh);
    cudaGetSymbolAddress((void**)&vth,  g_vth);
    cudaGetSymbolAddress((void**)&pf,   g_pf);
    cudaGetSymbolAddress((void**)&vhf,  g_vhf);

    cudaFuncSetAttribute(gemm_mma<0,0>, cudaFuncAttributeMaxDynamicSharedMemorySize, SMEM_MMA);
    cudaFuncSetAttribute(gemm_mma<0,1>, cudaFuncAttributeMaxDynamicSharedMemorySize, SMEM_MMA);
    cudaFuncSetAttribute(gemm_mma<1,0>, cudaFuncAttributeMaxDynamicSharedMemorySize, SMEM_MMA);
    cudaFuncSetAttribute(gemm_mma<2,1>, cudaFuncAttributeMaxDynamicSharedMemorySize, SMEM_MMA);

    // 1) fused conversion of x, Wqkv_w, out_w to fp16 + RoPE tables (one launch)
    {
        int n0 = (int)((size_t)M1 * DIMC / 4);
        int n1 = (int)((size_t)QKVN * DIMC / 4);
        int n2 = (int)((size_t)DIMC * DIMC / 4);
        int nconv = (n0 + n1 + n2) / 256;
        int ntab  = (SEQ * 512) / 256;
        conv3_tab<<<nconv + ntab, 256>>>(x, xf, n0, Wqkv_w, wqh, n1, out_w, owh, n2, nconv);
    }

    // 2) QKV = x @ Wqkv^T + b  -> fp16 qkv  [8192 x 6144 x 2048]
    gemm_mma<0,1><<<dim3(QKVN/128, M1/128, 1), 256, SMEM_MMA>>>(
        xf, wqh, Wqkv_b, qkvh,
        DIMC, DIMC, DIMC, QKVN, 0, 0, 0, 0, 1, 1.0f);

    // 3) fused RoPE + V transpose (vectorized): qf/kh fp16, kout/vout fp32, vth fp16
    rope_vt_fused<<<dim3(SEQ/32, 512/64, 8), dim3(32, 8)>>>(
        qkvh, qf, kh, kout, vout, vth);

    // 4) S = (1/32) q @ k^T  per head; causal via tile skip + index mask
    gemm_mma<1,0><<<dim3(SEQ/128, SEQ/128, 8), 256, SMEM_MMA>>>(
        qf, kh, nullptr, S,
        HDIM, HDIM, HDIM, SEQ,
        (long)SEQ*HDIM, (long)SEQ*HDIM, (long)SEQ*SEQ, 0, 1, 0.03125f);

    // 5) causal softmax -> fp16 P (zero-fill to PV K-limit)
    softmax_h<<<8 * SEQ, 256>>>(S, pf);

    // 6) VH = P @ V (via Vt), causal K-limit, longest-first; fp16 out to (B,L,D)
    gemm_mma<2,1><<<dim3(HDIM/128, SEQ/128, 8), 256, SMEM_MMA>>>(
        pf, vth, nullptr, vhf,
        SEQ, SEQ, SEQ, DIMC,
        (long)SEQ*SEQ, (long)HDIM*SEQ, (long)SEQ*DIMC, (long)HDIM, NHEADS, 1.0f);

    // 7) out = VH @ out_w^T + out_b  [8192 x 2048 x 2048]
    gemm_mma<0,0><<<dim3(DIMC/128, M1/128, 1), 256, SMEM_MMA>>>(
        vhf, owh, out_b, out,
        DIMC, DIMC, DIMC, DIMC, 0, 0, 0, 0, 1, 1.0f);
}